// round 9
// baseline (speedup 1.0000x reference)
#include <cuda_runtime.h>
#include <cuda_fp16.h>

typedef unsigned long long u64;

#define BD 16
#define ND 4
#define NF 481
#define TT 500
#define CC 16
#define HH 32
#define NSEQ (BD * NF)              // 7696
#define PROB_ELEMS (BD * NF * TT)   // 3,848,000

// conv output x: [n][t][c]
__device__ float g_x[(size_t)NSEQ * TT * CC];
// projected gates, fp16 (biases folded): [n][t][96] halfs:
//   [0:64)  = interleaved (r[j], z[j]) as half2 at half-offset 2j
//   [64:96) = n[j]
// +768 halfs pad for 4-deep prefetch overrun
__device__ __half g_xgh[(size_t)NSEQ * TT * 96 + 768];
// hidden-state history (fp16): [n][t][32]
__device__ __half g_hh[(size_t)NSEQ * TT * HH];

// ---------------------------------------------------------------------------
// helpers
// ---------------------------------------------------------------------------
__device__ __forceinline__ u64 pack2(float lo, float hi) {
    u64 r; asm("mov.b64 %0, {%1,%2};" : "=l"(r) : "f"(lo), "f"(hi)); return r;
}
__device__ __forceinline__ void unpack2(u64 v, float& lo, float& hi) {
    asm("mov.b64 {%0,%1}, %2;" : "=f"(lo), "=f"(hi) : "l"(v));
}
__device__ __forceinline__ void ffma2(u64& acc, u64 a, u64 b) {
    asm("fma.rn.f32x2 %0, %1, %2, %0;" : "+l"(acc) : "l"(a), "l"(b));
}
__device__ __forceinline__ float tanha(float x) {
    float y; asm("tanh.approx.f32 %0, %1;" : "=f"(y) : "f"(x)); return y;
}
__device__ __forceinline__ float sigma(float x) {
    return fmaf(0.5f, tanha(0.5f * x), 0.5f);
}

// ---------------------------------------------------------------------------
// Conv stage (unchanged): per frame (b,t).
// ---------------------------------------------------------------------------
__global__ __launch_bounds__(128) void conv_kernel(
    const float* __restrict__ feat,
    const float* __restrict__ w1, const float* __restrict__ b1, const float* __restrict__ p1,
    const float* __restrict__ w2, const float* __restrict__ b2, const float* __restrict__ p2)
{
    __shared__ float s_in[ND][NF + 12];
    __shared__ float s_mid[CC][NF + 8];
    __shared__ float s_w1[CC * ND * 9];
    __shared__ float s_w2[CC * CC * 5];
    __shared__ float s_b1[CC], s_b2[CC];
    __shared__ float s_a[2];

    const int tid = threadIdx.x;
    const int b = blockIdx.x / TT;
    const int t = blockIdx.x % TT;

    for (int i = tid; i < ND * (NF + 12); i += 128) (&s_in[0][0])[i] = 0.f;
    for (int i = tid; i < CC * (NF + 8); i += 128) (&s_mid[0][0])[i] = 0.f;
    for (int i = tid; i < CC * ND * 9; i += 128) s_w1[i] = w1[i];
    for (int i = tid; i < CC * CC * 5; i += 128) s_w2[i] = w2[i];
    if (tid < CC) { s_b1[tid] = b1[tid]; s_b2[tid] = b2[tid]; }
    if (tid == 0) { s_a[0] = p1[0]; s_a[1] = p2[0]; }
    __syncthreads();

    for (int i = tid; i < ND * NF; i += 128) {
        const int d = i / NF, f = i - d * NF;
        s_in[d][f + 4] = feat[((size_t)(b * ND + d) * NF + f) * TT + t];
    }
    __syncthreads();

    const int c = tid & 15;
    const float a1 = s_a[0], a2 = s_a[1];

    {
        float wr[36];
        #pragma unroll
        for (int q = 0; q < 36; q++) wr[q] = s_w1[c * 36 + q];
        const float bias = s_b1[c];

        for (int fg = (tid >> 4); fg < 121; fg += 8) {
            const int f0 = fg * 4;
            float acc[4] = {bias, bias, bias, bias};
            #pragma unroll
            for (int d = 0; d < ND; d++) {
                float win[12];
                #pragma unroll
                for (int q = 0; q < 12; q++) win[q] = s_in[d][f0 + q];
                #pragma unroll
                for (int j = 0; j < 4; j++)
                    #pragma unroll
                    for (int k = 0; k < 9; k++)
                        acc[j] += win[j + k] * wr[d * 9 + k];
            }
            #pragma unroll
            for (int j = 0; j < 4; j++) {
                if (f0 + j < NF) {
                    const float v = acc[j];
                    s_mid[c][f0 + j + 2] = (v >= 0.f) ? v : a1 * v;
                }
            }
        }
    }
    __syncthreads();

    {
        float wr[80];
        #pragma unroll
        for (int q = 0; q < 80; q++) wr[q] = s_w2[c * 80 + q];
        const float bias = s_b2[c];

        for (int fg = (tid >> 4); fg < 121; fg += 8) {
            const int f0 = fg * 4;
            float acc[4] = {bias, bias, bias, bias};
            #pragma unroll
            for (int ci = 0; ci < CC; ci++) {
                float win[8];
                #pragma unroll
                for (int q = 0; q < 8; q++) win[q] = s_mid[ci][f0 + q];
                #pragma unroll
                for (int j = 0; j < 4; j++)
                    #pragma unroll
                    for (int k = 0; k < 5; k++)
                        acc[j] += win[j + k] * wr[ci * 5 + k];
            }
            #pragma unroll
            for (int j = 0; j < 4; j++) {
                if (f0 + j < NF) {
                    float v = acc[j];
                    v = (v >= 0.f) ? v : a2 * v;
                    g_x[((size_t)(b * NF + f0 + j) * TT + t) * CC + c] = v;
                }
            }
        }
    }
}

// ---------------------------------------------------------------------------
// Projection (unchanged): xg = x @ W_ih^T + folded biases, stored fp16.
// ---------------------------------------------------------------------------
__global__ __launch_bounds__(128) void proj_kernel(
    const float* __restrict__ w_ih,
    const float* __restrict__ b_ih, const float* __restrict__ b_hh)
{
    const int n = (blockIdx.x * blockDim.x + threadIdx.x) >> 5;
    const int j = threadIdx.x & 31;
    if (n >= NSEQ) return;

    u64 wr[8], wz[8], wn[8];
    const u64* pr = (const u64*)(w_ih + (size_t)j * 16);
    const u64* pz = (const u64*)(w_ih + (size_t)(32 + j) * 16);
    const u64* pn = (const u64*)(w_ih + (size_t)(64 + j) * 16);
    #pragma unroll
    for (int p = 0; p < 8; p++) { wr[p] = pr[p]; wz[p] = pz[p]; wn[p] = pn[p]; }

    const float br = b_ih[j]      + b_hh[j];
    const float bz = b_ih[32 + j] + b_hh[32 + j];
    const float bn = b_ih[64 + j];

    const ulonglong2* __restrict__ xp = (const ulonglong2*)(g_x + (size_t)n * TT * CC);
    __half* __restrict__ og = g_xgh + (size_t)n * TT * 96;

    for (int t = 0; t < TT; t++) {
        ulonglong2 v0 = xp[t * 4 + 0], v1 = xp[t * 4 + 1],
                   v2 = xp[t * 4 + 2], v3 = xp[t * 4 + 3];
        u64 xq[8] = {v0.x, v0.y, v1.x, v1.y, v2.x, v2.y, v3.x, v3.y};

        u64 ar = pack2(br, 0.f), az = pack2(bz, 0.f), an = pack2(bn, 0.f);
        #pragma unroll
        for (int p = 0; p < 8; p++) {
            ffma2(ar, wr[p], xq[p]);
            ffma2(az, wz[p], xq[p]);
            ffma2(an, wn[p], xq[p]);
        }
        float l0, h0_, l1, h1_, l2, h2_;
        unpack2(ar, l0, h0_); unpack2(az, l1, h1_); unpack2(an, l2, h2_);

        __half* ot = og + (size_t)t * 96;
        ((__half2*)ot)[j] = __floats2half2_rn(l0 + h0_, l1 + h1_);  // (r, z)
        ot[64 + j] = __float2half_rn(l2 + h2_);                      // n
    }
}

// ---------------------------------------------------------------------------
// GRU: TWO sequences per warp (shared W_hh registers), lane j = hidden unit j.
// 4-deep fp16 xg prefetch ring per sequence; h streamed to g_hh as fp16.
// ---------------------------------------------------------------------------
__global__ __launch_bounds__(128, 2) void gru_kernel(
    const float* __restrict__ h0,
    const float* __restrict__ w_hh, const float* __restrict__ b_hh,
    float* __restrict__ out)
{
    __shared__ __align__(16) float s_h[2][4][2][32];   // [buf][warp][seq][unit]

    const int w = threadIdx.x >> 5;
    const int j = threadIdx.x & 31;
    const int nA = blockIdx.x * 8 + w * 2;
    const int nB = nA + 1;

    u64 whr[16], whz[16], whn[16];
    const u64* qr = (const u64*)(w_hh + (size_t)j * 32);
    const u64* qz = (const u64*)(w_hh + (size_t)(32 + j) * 32);
    const u64* qn = (const u64*)(w_hh + (size_t)(64 + j) * 32);
    #pragma unroll
    for (int p = 0; p < 16; p++) { whr[p] = qr[p]; whz[p] = qz[p]; whn[p] = qn[p]; }

    const float bhn = b_hh[64 + j];

    float hA = h0[nA * HH + j];
    float hB = h0[nB * HH + j];
    s_h[0][w][0][j] = hA;
    s_h[0][w][1][j] = hB;
    __syncwarp();

    const __half* __restrict__ xgpA = g_xgh + (size_t)nA * TT * 96;
    const __half* __restrict__ xgpB = g_xgh + (size_t)nB * TT * 96;
    __half* __restrict__ houtA = g_hh + (size_t)nA * TT * HH + j;
    __half* __restrict__ houtB = g_hh + (size_t)nB * TT * HH + j;

    // 4-deep prefetch rings
    __half2 bufRZA[4], bufRZB[4];
    __half  bufNA[4],  bufNB[4];
    #pragma unroll
    for (int p = 0; p < 4; p++) {
        const __half* qA = xgpA + (size_t)p * 96;
        const __half* qB = xgpB + (size_t)p * 96;
        bufRZA[p] = ((const __half2*)qA)[j]; bufNA[p] = qA[64 + j];
        bufRZB[p] = ((const __half2*)qB)[j]; bufNB[p] = qB[64 + j];
    }

#define GRU_STEP(S)                                                            \
    {                                                                          \
        const float2 xrzA = __half22float2(bufRZA[S]);                         \
        const float2 xrzB = __half22float2(bufRZB[S]);                         \
        const float xnA = __half2float(bufNA[S]);                              \
        const float xnB = __half2float(bufNB[S]);                              \
        {   /* prefetch t = tb + 4 + S (array padded past TT) */               \
            const __half* qA = xgpA + (size_t)(tb + 4 + (S)) * 96;             \
            const __half* qB = xgpB + (size_t)(tb + 4 + (S)) * 96;             \
            bufRZA[S] = ((const __half2*)qA)[j]; bufNA[S] = qA[64 + j];        \
            bufRZB[S] = ((const __half2*)qB)[j]; bufNB[S] = qB[64 + j];        \
        }                                                                      \
        const ulonglong2* hvA = (const ulonglong2*)s_h[(S) & 1][w][0];         \
        const ulonglong2* hvB = (const ulonglong2*)s_h[(S) & 1][w][1];         \
        u64 hpA[16], hpB[16];                                                  \
        _Pragma("unroll")                                                      \
        for (int p = 0; p < 8; p++) {                                          \
            ulonglong2 va = hvA[p]; hpA[2 * p] = va.x; hpA[2 * p + 1] = va.y;  \
            ulonglong2 vb = hvB[p]; hpB[2 * p] = vb.x; hpB[2 * p + 1] = vb.y;  \
        }                                                                      \
        const u64 zz = pack2(0.f, 0.f);                                        \
        u64 arA0 = pack2(xrzA.x, 0.f), azA0 = pack2(xrzA.y, 0.f),              \
            anA0 = pack2(bhn, 0.f), arA1 = zz, azA1 = zz, anA1 = zz;           \
        u64 arB0 = pack2(xrzB.x, 0.f), azB0 = pack2(xrzB.y, 0.f),              \
            anB0 = pack2(bhn, 0.f), arB1 = zz, azB1 = zz, anB1 = zz;           \
        _Pragma("unroll")                                                      \
        for (int p = 0; p < 8; p++) {                                          \
            ffma2(arA0, whr[2 * p],     hpA[2 * p]);                           \
            ffma2(arA1, whr[2 * p + 1], hpA[2 * p + 1]);                       \
            ffma2(arB0, whr[2 * p],     hpB[2 * p]);                           \
            ffma2(arB1, whr[2 * p + 1], hpB[2 * p + 1]);                       \
            ffma2(azA0, whz[2 * p],     hpA[2 * p]);                           \
            ffma2(azA1, whz[2 * p + 1], hpA[2 * p + 1]);                       \
            ffma2(azB0, whz[2 * p],     hpB[2 * p]);                           \
            ffma2(azB1, whz[2 * p + 1], hpB[2 * p + 1]);                       \
            ffma2(anA0, whn[2 * p],     hpA[2 * p]);                           \
            ffma2(anA1, whn[2 * p + 1], hpA[2 * p + 1]);                       \
            ffma2(anB0, whn[2 * p],     hpB[2 * p]);                           \
            ffma2(anB1, whn[2 * p + 1], hpB[2 * p + 1]);                       \
        }                                                                      \
        float t0, t1, t2, t3;                                                  \
        unpack2(arA0, t0, t1); unpack2(arA1, t2, t3);                          \
        const float rA = sigma((t0 + t1) + (t2 + t3));                         \
        unpack2(azA0, t0, t1); unpack2(azA1, t2, t3);                          \
        const float zA = sigma((t0 + t1) + (t2 + t3));                         \
        unpack2(anA0, t0, t1); unpack2(anA1, t2, t3);                          \
        const float gnA = (t0 + t1) + (t2 + t3);                               \
        unpack2(arB0, t0, t1); unpack2(arB1, t2, t3);                          \
        const float rB = sigma((t0 + t1) + (t2 + t3));                         \
        unpack2(azB0, t0, t1); unpack2(azB1, t2, t3);                          \
        const float zB = sigma((t0 + t1) + (t2 + t3));                         \
        unpack2(anB0, t0, t1); unpack2(anB1, t2, t3);                          \
        const float gnB = (t0 + t1) + (t2 + t3);                               \
        const float nnA = tanha(fmaf(rA, gnA, xnA));                           \
        const float nnB = tanha(fmaf(rB, gnB, xnB));                           \
        hA = fmaf(zA, hA - nnA, nnA);                                          \
        hB = fmaf(zB, hB - nnB, nnB);                                          \
        houtA[(size_t)(tb + (S)) * HH] = __float2half_rn(hA);                  \
        houtB[(size_t)(tb + (S)) * HH] = __float2half_rn(hB);                  \
        s_h[((S) & 1) ^ 1][w][0][j] = hA;                                      \
        s_h[((S) & 1) ^ 1][w][1][j] = hB;                                      \
        __syncwarp();                                                          \
    }

    for (int tb = 0; tb < TT; tb += 4) {
        GRU_STEP(0)
        GRU_STEP(1)
        GRU_STEP(2)
        GRU_STEP(3)
    }
#undef GRU_STEP

    out[(size_t)PROB_ELEMS + (size_t)nA * HH + j] = hA;
    out[(size_t)PROB_ELEMS + (size_t)nB * HH + j] = hB;
}

// ---------------------------------------------------------------------------
// FC epilogue (unchanged): prob[n][t] = sigmoid(fc_w . h[n][t] + fc_b).
// ---------------------------------------------------------------------------
__global__ __launch_bounds__(256) void fc_kernel(
    const float* __restrict__ fc_w, const float* __restrict__ fc_b,
    float* __restrict__ out)
{
    __shared__ float s_w[HH];
    if (threadIdx.x < HH) s_w[threadIdx.x] = fc_w[threadIdx.x];
    __syncthreads();

    const size_t idx = (size_t)blockIdx.x * 256 + threadIdx.x;
    if (idx >= (size_t)PROB_ELEMS) return;

    const uint4* hp = (const uint4*)(g_hh + idx * HH);
    float acc = fc_b[0];
    #pragma unroll
    for (int q = 0; q < 4; q++) {
        const uint4 u = hp[q];
        const unsigned uu[4] = {u.x, u.y, u.z, u.w};
        #pragma unroll
        for (int m = 0; m < 4; m++) {
            const float2 v = __half22float2(*(const __half2*)&uu[m]);
            acc += v.x * s_w[q * 8 + m * 2] + v.y * s_w[q * 8 + m * 2 + 1];
        }
    }
    out[idx] = sigma(acc);
}

extern "C" void kernel_launch(void* const* d_in, const int* in_sizes, int n_in,
                              void* d_out, int out_size) {
    const float* feat = (const float*)d_in[0];
    const float* h0   = (const float*)d_in[1];
    const float* w1   = (const float*)d_in[2];
    const float* b1   = (const float*)d_in[3];
    const float* p1   = (const float*)d_in[4];
    const float* w2   = (const float*)d_in[5];
    const float* b2   = (const float*)d_in[6];
    const float* p2   = (const float*)d_in[7];
    const float* wih  = (const float*)d_in[8];
    const float* whh  = (const float*)d_in[9];
    const float* bih  = (const float*)d_in[10];
    const float* bhh  = (const float*)d_in[11];
    const float* fcw  = (const float*)d_in[12];
    const float* fcb  = (const float*)d_in[13];
    float* out = (float*)d_out;

    conv_kernel<<<BD * TT, 128>>>(feat, w1, b1, p1, w2, b2, p2);
    proj_kernel<<<NSEQ / 4, 128>>>(wih, bih, bhh);
    gru_kernel<<<NSEQ / 8, 128>>>(h0, whh, bhh, out);
    fc_kernel<<<(PROB_ELEMS + 255) / 256, 256>>>(fcw, fcb, out);
}

// round 16
// speedup vs baseline: 1.0277x; 1.0277x over previous
#include <cuda_runtime.h>
#include <cuda_fp16.h>

typedef unsigned long long u64;

#define BD 16
#define ND 4
#define NF 481
#define TT 500
#define CC 16
#define HH 32
#define NSEQ (BD * NF)              // 7696
#define PROB_ELEMS (BD * NF * TT)   // 3,848,000
#define FPAD 496                    // padded smem row (floats), 16B-aligned rows

// conv output x: [n][t][c]
__device__ float g_x[(size_t)NSEQ * TT * CC];
// projected gates, fp16 (biases folded): [n][t][96] halfs:
//   [0:64)  = interleaved (r[j], z[j]) as half2 at half-offset 2j
//   [64:96) = n[j]
// +768 halfs pad for 4-deep prefetch overrun
__device__ __half g_xgh[(size_t)NSEQ * TT * 96 + 768];
// hidden-state history (fp16): [n][t][32]
__device__ __half g_hh[(size_t)NSEQ * TT * HH];

// ---------------------------------------------------------------------------
// helpers
// ---------------------------------------------------------------------------
__device__ __forceinline__ u64 pack2(float lo, float hi) {
    u64 r; asm("mov.b64 %0, {%1,%2};" : "=l"(r) : "f"(lo), "f"(hi)); return r;
}
__device__ __forceinline__ void unpack2(u64 v, float& lo, float& hi) {
    asm("mov.b64 {%0,%1}, %2;" : "=f"(lo), "=f"(hi) : "l"(v));
}
__device__ __forceinline__ void ffma2(u64& acc, u64 a, u64 b) {
    asm("fma.rn.f32x2 %0, %1, %2, %0;" : "+l"(acc) : "l"(a), "l"(b));
}
__device__ __forceinline__ float tanha(float x) {
    float y; asm("tanh.approx.f32 %0, %1;" : "=f"(y) : "f"(x)); return y;
}
__device__ __forceinline__ float sigma(float x) {
    return fmaf(0.5f, tanha(0.5f * x), 0.5f);
}

// ---------------------------------------------------------------------------
// Conv stage: per frame (b,t). 16B-aligned smem rows + LDS.128 windows.
// ---------------------------------------------------------------------------
__global__ __launch_bounds__(128) void conv_kernel(
    const float* __restrict__ feat,
    const float* __restrict__ w1, const float* __restrict__ b1, const float* __restrict__ p1,
    const float* __restrict__ w2, const float* __restrict__ b2, const float* __restrict__ p2)
{
    __shared__ __align__(16) float s_in[ND][FPAD];    // data at [f+4], zero elsewhere
    __shared__ __align__(16) float s_mid[CC][FPAD];   // data at [f+2], zero elsewhere
    __shared__ float s_w1[CC * ND * 9];
    __shared__ float s_w2[CC * CC * 5];
    __shared__ float s_b1[CC], s_b2[CC];
    __shared__ float s_a[2];

    const int tid = threadIdx.x;
    const int b = blockIdx.x / TT;
    const int t = blockIdx.x % TT;

    for (int i = tid; i < ND * FPAD; i += 128) (&s_in[0][0])[i] = 0.f;
    for (int i = tid; i < CC * FPAD; i += 128) (&s_mid[0][0])[i] = 0.f;
    for (int i = tid; i < CC * ND * 9; i += 128) s_w1[i] = w1[i];
    for (int i = tid; i < CC * CC * 5; i += 128) s_w2[i] = w2[i];
    if (tid < CC) { s_b1[tid] = b1[tid]; s_b2[tid] = b2[tid]; }
    if (tid == 0) { s_a[0] = p1[0]; s_a[1] = p2[0]; }
    __syncthreads();

    for (int i = tid; i < ND * NF; i += 128) {
        const int d = i / NF, f = i - d * NF;
        s_in[d][f + 4] = feat[((size_t)(b * ND + d) * NF + f) * TT + t];
    }
    __syncthreads();

    const int c = tid & 15;
    const float a1 = s_a[0], a2 = s_a[1];

    {
        float wr[36];
        #pragma unroll
        for (int q = 0; q < 36; q++) wr[q] = s_w1[c * 36 + q];
        const float bias = s_b1[c];

        for (int fg = (tid >> 4); fg < 121; fg += 8) {
            const int f0 = fg * 4;                     // 16B-aligned float index
            float acc[4] = {bias, bias, bias, bias};
            #pragma unroll
            for (int d = 0; d < ND; d++) {
                const float4* rp = (const float4*)&s_in[d][f0];
                const float4 v0 = rp[0], v1 = rp[1], v2 = rp[2];
                const float win[12] = {v0.x, v0.y, v0.z, v0.w,
                                       v1.x, v1.y, v1.z, v1.w,
                                       v2.x, v2.y, v2.z, v2.w};
                #pragma unroll
                for (int j = 0; j < 4; j++)
                    #pragma unroll
                    for (int k = 0; k < 9; k++)
                        acc[j] += win[j + k] * wr[d * 9 + k];
            }
            #pragma unroll
            for (int j = 0; j < 4; j++) {
                if (f0 + j < NF) {
                    const float v = acc[j];
                    s_mid[c][f0 + j + 2] = (v >= 0.f) ? v : a1 * v;
                }
            }
        }
    }
    __syncthreads();

    {
        float wr[80];
        #pragma unroll
        for (int q = 0; q < 80; q++) wr[q] = s_w2[c * 80 + q];
        const float bias = s_b2[c];

        for (int fg = (tid >> 4); fg < 121; fg += 8) {
            const int f0 = fg * 4;
            float acc[4] = {bias, bias, bias, bias};
            #pragma unroll
            for (int ci = 0; ci < CC; ci++) {
                const float4* rp = (const float4*)&s_mid[ci][f0];
                const float4 v0 = rp[0], v1 = rp[1];
                const float win[8] = {v0.x, v0.y, v0.z, v0.w,
                                      v1.x, v1.y, v1.z, v1.w};
                #pragma unroll
                for (int j = 0; j < 4; j++)
                    #pragma unroll
                    for (int k = 0; k < 5; k++)
                        acc[j] += win[j + k] * wr[ci * 5 + k];
            }
            #pragma unroll
            for (int j = 0; j < 4; j++) {
                if (f0 + j < NF) {
                    float v = acc[j];
                    v = (v >= 0.f) ? v : a2 * v;
                    g_x[((size_t)(b * NF + f0 + j) * TT + t) * CC + c] = v;
                }
            }
        }
    }
}

// ---------------------------------------------------------------------------
// Projection (unchanged): xg = x @ W_ih^T + folded biases, stored fp16.
// ---------------------------------------------------------------------------
__global__ __launch_bounds__(128) void proj_kernel(
    const float* __restrict__ w_ih,
    const float* __restrict__ b_ih, const float* __restrict__ b_hh)
{
    const int n = (blockIdx.x * blockDim.x + threadIdx.x) >> 5;
    const int j = threadIdx.x & 31;
    if (n >= NSEQ) return;

    u64 wr[8], wz[8], wn[8];
    const u64* pr = (const u64*)(w_ih + (size_t)j * 16);
    const u64* pz = (const u64*)(w_ih + (size_t)(32 + j) * 16);
    const u64* pn = (const u64*)(w_ih + (size_t)(64 + j) * 16);
    #pragma unroll
    for (int p = 0; p < 8; p++) { wr[p] = pr[p]; wz[p] = pz[p]; wn[p] = pn[p]; }

    const float br = b_ih[j]      + b_hh[j];
    const float bz = b_ih[32 + j] + b_hh[32 + j];
    const float bn = b_ih[64 + j];

    const ulonglong2* __restrict__ xp = (const ulonglong2*)(g_x + (size_t)n * TT * CC);
    __half* __restrict__ og = g_xgh + (size_t)n * TT * 96;

    for (int t = 0; t < TT; t++) {
        ulonglong2 v0 = xp[t * 4 + 0], v1 = xp[t * 4 + 1],
                   v2 = xp[t * 4 + 2], v3 = xp[t * 4 + 3];
        u64 xq[8] = {v0.x, v0.y, v1.x, v1.y, v2.x, v2.y, v3.x, v3.y};

        u64 ar = pack2(br, 0.f), az = pack2(bz, 0.f), an = pack2(bn, 0.f);
        #pragma unroll
        for (int p = 0; p < 8; p++) {
            ffma2(ar, wr[p], xq[p]);
            ffma2(az, wz[p], xq[p]);
            ffma2(an, wn[p], xq[p]);
        }
        float l0, h0_, l1, h1_, l2, h2_;
        unpack2(ar, l0, h0_); unpack2(az, l1, h1_); unpack2(an, l2, h2_);

        __half* ot = og + (size_t)t * 96;
        ((__half2*)ot)[j] = __floats2half2_rn(l0 + h0_, l1 + h1_);  // (r, z)
        ot[64 + j] = __float2half_rn(l2 + h2_);                      // n
    }
}

// ---------------------------------------------------------------------------
// GRU: one warp per sequence, lane j = hidden unit j. 4-deep fp16 xg prefetch
// ring (2 LDGs/step), h streamed to g_hh as fp16.
// NO min-blocks clamp: let ptxas take its no-spill register budget.
// ---------------------------------------------------------------------------
__global__ __launch_bounds__(128) void gru_kernel(
    const float* __restrict__ h0,
    const float* __restrict__ w_hh, const float* __restrict__ b_hh,
    float* __restrict__ out)
{
    __shared__ __align__(16) float s_h[2][4][32];

    const int w = threadIdx.x >> 5;
    const int j = threadIdx.x & 31;
    const int n = blockIdx.x * 4 + w;

    u64 whr[16], whz[16], whn[16];
    const u64* qr = (const u64*)(w_hh + (size_t)j * 32);
    const u64* qz = (const u64*)(w_hh + (size_t)(32 + j) * 32);
    const u64* qn = (const u64*)(w_hh + (size_t)(64 + j) * 32);
    #pragma unroll
    for (int p = 0; p < 16; p++) { whr[p] = qr[p]; whz[p] = qz[p]; whn[p] = qn[p]; }

    const float bhn = b_hh[64 + j];

    float h = h0[n * HH + j];
    s_h[0][w][j] = h;
    __syncwarp();

    const __half* __restrict__ xgp = g_xgh + (size_t)n * TT * 96;
    __half* __restrict__ hout = g_hh + (size_t)n * TT * HH + j;

    // 4-deep prefetch ring (raw bits)
    __half2 bufRZ[4];
    __half  bufN[4];
    #pragma unroll
    for (int p = 0; p < 4; p++) {
        const __half* q = xgp + (size_t)p * 96;
        bufRZ[p] = ((const __half2*)q)[j];
        bufN[p]  = q[64 + j];
    }

#define GRU_STEP(S)                                                            \
    {                                                                          \
        const float2 xrz = __half22float2(bufRZ[S]);                           \
        const float xn = __half2float(bufN[S]);                                \
        {   /* prefetch t = tb + 4 + S (array padded past TT) */               \
            const __half* q = xgp + (size_t)(tb + 4 + (S)) * 96;               \
            bufRZ[S] = ((const __half2*)q)[j];                                 \
            bufN[S]  = q[64 + j];                                              \
        }                                                                      \
        const ulonglong2* hv = (const ulonglong2*)s_h[(S) & 1][w];             \
        ulonglong2 a0 = hv[0], a1 = hv[1], a2 = hv[2], a3 = hv[3],             \
                   a4 = hv[4], a5 = hv[5], a6 = hv[6], a7 = hv[7];             \
        u64 hp[16] = {a0.x, a0.y, a1.x, a1.y, a2.x, a2.y, a3.x, a3.y,          \
                      a4.x, a4.y, a5.x, a5.y, a6.x, a6.y, a7.x, a7.y};         \
        u64 ar0 = pack2(xrz.x, 0.f), az0 = pack2(xrz.y, 0.f),                  \
            an0 = pack2(bhn, 0.f);                                             \
        u64 ar1 = pack2(0.f, 0.f), az1 = ar1, an1 = ar1;                       \
        _Pragma("unroll")                                                      \
        for (int p = 0; p < 8; p++) {                                          \
            ffma2(ar0, whr[2 * p],     hp[2 * p]);                             \
            ffma2(ar1, whr[2 * p + 1], hp[2 * p + 1]);                         \
            ffma2(az0, whz[2 * p],     hp[2 * p]);                             \
            ffma2(az1, whz[2 * p + 1], hp[2 * p + 1]);                         \
            ffma2(an0, whn[2 * p],     hp[2 * p]);                             \
            ffma2(an1, whn[2 * p + 1], hp[2 * p + 1]);                         \
        }                                                                      \
        float r0l, r0h, r1l, r1h, z0l, z0h, z1l, z1h, n0l, n0h, n1l, n1h;      \
        unpack2(ar0, r0l, r0h); unpack2(ar1, r1l, r1h);                        \
        unpack2(az0, z0l, z0h); unpack2(az1, z1l, z1h);                        \
        unpack2(an0, n0l, n0h); unpack2(an1, n1l, n1h);                        \
        const float r  = sigma((r0l + r0h) + (r1l + r1h));                     \
        const float z  = sigma((z0l + z0h) + (z1l + z1h));                     \
        const float gn = (n0l + n0h) + (n1l + n1h);                            \
        const float nn = tanha(fmaf(r, gn, xn));                               \
        h = fmaf(z, h - nn, nn);                                               \
        hout[(size_t)(tb + (S)) * HH] = __float2half_rn(h);                    \
        s_h[((S) & 1) ^ 1][w][j] = h;                                          \
        __syncwarp();                                                          \
    }

    for (int tb = 0; tb < TT; tb += 4) {
        GRU_STEP(0)
        GRU_STEP(1)
        GRU_STEP(2)
        GRU_STEP(3)
    }
#undef GRU_STEP

    out[(size_t)PROB_ELEMS + (size_t)n * HH + j] = h;
}

// ---------------------------------------------------------------------------
// FC epilogue (unchanged): prob[n][t] = sigmoid(fc_w . h[n][t] + fc_b).
// ---------------------------------------------------------------------------
__global__ __launch_bounds__(256) void fc_kernel(
    const float* __restrict__ fc_w, const float* __restrict__ fc_b,
    float* __restrict__ out)
{
    __shared__ float s_w[HH];
    if (threadIdx.x < HH) s_w[threadIdx.x] = fc_w[threadIdx.x];
    __syncthreads();

    const size_t idx = (size_t)blockIdx.x * 256 + threadIdx.x;
    if (idx >= (size_t)PROB_ELEMS) return;

    const uint4* hp = (const uint4*)(g_hh + idx * HH);
    float acc = fc_b[0];
    #pragma unroll
    for (int q = 0; q < 4; q++) {
        const uint4 u = hp[q];
        const unsigned uu[4] = {u.x, u.y, u.z, u.w};
        #pragma unroll
        for (int m = 0; m < 4; m++) {
            const float2 v = __half22float2(*(const __half2*)&uu[m]);
            acc += v.x * s_w[q * 8 + m * 2] + v.y * s_w[q * 8 + m * 2 + 1];
        }
    }
    out[idx] = sigma(acc);
}

extern "C" void kernel_launch(void* const* d_in, const int* in_sizes, int n_in,
                              void* d_out, int out_size) {
    const float* feat = (const float*)d_in[0];
    const float* h0   = (const float*)d_in[1];
    const float* w1   = (const float*)d_in[2];
    const float* b1   = (const float*)d_in[3];
    const float* p1   = (const float*)d_in[4];
    const float* w2   = (const float*)d_in[5];
    const float* b2   = (const float*)d_in[6];
    const float* p2   = (const float*)d_in[7];
    const float* wih  = (const float*)d_in[8];
    const float* whh  = (const float*)d_in[9];
    const float* bih  = (const float*)d_in[10];
    const float* bhh  = (const float*)d_in[11];
    const float* fcw  = (const float*)d_in[12];
    const float* fcb  = (const float*)d_in[13];
    float* out = (float*)d_out;

    conv_kernel<<<BD * TT, 128>>>(feat, w1, b1, p1, w2, b2, p2);
    proj_kernel<<<NSEQ / 4, 128>>>(wih, bih, bhh);
    gru_kernel<<<NSEQ / 4, 128>>>(h0, whh, bhh, out);
    fc_kernel<<<(PROB_ELEMS + 255) / 256, 256>>>(fcw, fcb, out);
}